// round 5
// baseline (speedup 1.0000x reference)
#include <cuda_runtime.h>

typedef unsigned long long ull;

#define D_IN 992
#define HID  32
#define W1   6
#define NB   12
#define KC   32               // k-chunk
#define RPB  128              // rows per block
#define NTHR 256
#define NTILES (D_IN / KC)    // 31
#define ASTR 132              // float stride of As row (16B-aligned, padded)
#define WSTR 34               // ull stride of Wd row (16B-aligned, padded)

__device__ __forceinline__ ull ffma2(ull a, ull b, ull c) {
    ull d;
    asm("fma.rn.f32x2 %0, %1, %2, %3;" : "=l"(d) : "l"(a), "l"(b), "l"(c));
    return d;
}

__device__ __forceinline__ ull dupf(float f) {
    unsigned r = __float_as_uint(f);
    return (((ull)r) << 32) | (ull)r;
}

// Compact degree-4 uniform B-spline: the 5 nonzero basis values + masked,
// clamped coefficient indices. Knots t_j = (j-4)*0.25 - 1  <=>  u=(x+2)*4.
__device__ __forceinline__ void basis5m(float x, float Bv[5], int ix[5]) {
    float u  = (x + 2.0f) * 4.0f;
    float fj = floorf(u);
    int   j0 = (int)fj;
    float s  = u - fj;                 // in [0,1)
    float B0, B1, B2, B3, B4;
    // p=1
    B1 = s;  B0 = 1.0f - s;
    // p=2
    B2 = 0.5f * (s * B1);
    B1 = 0.5f * ((s + 1.0f) * B0 + (2.0f - s) * B1);
    B0 = 0.5f * ((1.0f - s) * B0);
    // p=3
    const float i3 = (1.0f / 3.0f);
    B3 = i3 * (s * B2);
    B2 = i3 * ((s + 1.0f) * B1 + (3.0f - s) * B2);
    B1 = i3 * ((s + 2.0f) * B0 + (2.0f - s) * B1);
    B0 = i3 * ((1.0f - s) * B0);
    // p=4
    B4 = 0.25f * (s * B3);
    B3 = 0.25f * ((s + 1.0f) * B2 + (4.0f - s) * B3);
    B2 = 0.25f * ((s + 2.0f) * B1 + (3.0f - s) * B2);
    B1 = 0.25f * ((s + 3.0f) * B0 + (2.0f - s) * B1);
    B0 = 0.25f * ((1.0f - s) * B0);
    const bool vr = (j0 >= 0) && (j0 < 16);   // x in [-2,2) else all-zero
    float Bt[5] = {B0, B1, B2, B3, B4};
    #pragma unroll
    for (int m = 0; m < 5; m++) {
        int  id = j0 - 4 + m;                 // basis index into 0..11
        bool v  = vr && (id >= 0) && (id < 12);
        ix[m] = v ? id : 0;
        Bv[m] = v ? Bt[m] : 0.0f;
    }
}

__device__ __forceinline__ float dot5(const float* __restrict__ c,
                                      const float Bv[5], const int ix[5]) {
    float s = Bv[0] * c[ix[0]];
    s = fmaf(Bv[1], c[ix[1]], s);
    s = fmaf(Bv[2], c[ix[2]], s);
    s = fmaf(Bv[3], c[ix[3]], s);
    s = fmaf(Bv[4], c[ix[4]], s);
    return s;
}

__device__ __forceinline__ float silu_f(float x) {
    return x / (1.0f + __expf(-x));
}

__global__ __launch_bounds__(NTHR, 2)
void kan_fused_kernel(const float* __restrict__ node_rep,
                      const float* __restrict__ mlp_w,
                      const float* __restrict__ mlp_b,
                      const float* __restrict__ coef0,
                      const float* __restrict__ wb0,
                      const float* __restrict__ ws0,
                      const float* __restrict__ b0,
                      const float* __restrict__ coef1,
                      const float* __restrict__ wb1,
                      const float* __restrict__ ws1,
                      const float* __restrict__ b1,
                      float* __restrict__ out, int n)
{
    // GEMM tiles (As + Wd) aliased with Hs: GEMM region dead once hidden done.
    __shared__ __align__(16) char buf[KC * ASTR * 4 + KC * WSTR * 8];   // 25600B
    float (*As)[ASTR]     = (float (*)[ASTR])buf;                       // [32][132]
    ull   (*Wd)[WSTR]     = (ull   (*)[WSTR])(buf + KC * ASTR * 4);     // [32][34]
    float (*Hs)[HID + 1]  = (float (*)[HID + 1])buf;                    // [128][33]

    __shared__ __align__(16) float csc0[HID][W1][NB];   // coef0 * ws0
    __shared__ float wb0s[HID][W1];
    __shared__ float part[RPB][2][W1];
    __shared__ __align__(16) float csc1[W1][NB];        // coef1 * ws1
    __shared__ float wb1s[W1];
    __shared__ float b0s[W1];
    __shared__ float mlpbs[HID];
    __shared__ float b1s;

    const int tid  = threadIdx.x;
    const int row0 = blockIdx.x * RPB;

    // ---- stage small params (prescale spline coefs by w_sp) ----
    for (int idx = tid; idx < HID * W1 * NB; idx += NTHR)
        (&csc0[0][0][0])[idx] = coef0[idx] * ws0[idx / NB];
    if (tid < HID * W1) (&wb0s[0][0])[tid] = wb0[tid];
    if (tid < W1 * NB)  (&csc1[0][0])[tid] = coef1[tid] * ws1[tid / NB];
    if (tid < W1) { wb1s[tid] = wb1[tid]; b0s[tid] = b0[tid]; }
    if (tid < HID) mlpbs[tid] = mlp_b[tid];
    if (tid == 0) b1s = b1[0];

    // ---- GEMM thread geometry: warp owns 16 rows x 32 cols ----
    const int w  = tid >> 5;            // warp 0..7 -> rows w*16..w*16+15
    const int rq = (tid >> 3) & 3;      // 4-row patch within warp rows
    const int cq = tid & 7;             // 4-col patch (cols cq*4..cq*4+3)
    const int R0 = w * 16 + rq * 4;

    ull acc[4][2];                      // [col][row-ull]; 16 regs
    #pragma unroll
    for (int c = 0; c < 4; c++) { acc[c][0] = 0ull; acc[c][1] = 0ull; }

    // loader coordinates (identical to R1's proven staging)
    const int lc  = tid & 7;       // float4 chunk of a 32-k row
    const int lr0 = tid >> 3;      // base row (r = lr0 + 32j)
    const int wk  = tid >> 3;      // W: k row
    const int wc  = tid & 7;       // W: float4 chunk
    const int ssw = ((lc >> 1) & 1) * 8;   // store-side row swizzle (bit3 of k)

    float4 pa[4];
    float4 pw;

    // prologue: prefetch tile 0
    {
        #pragma unroll
        for (int j = 0; j < 4; j++) {
            int grow = row0 + lr0 + 32 * j;
            pa[j] = make_float4(0.f, 0.f, 0.f, 0.f);
            if (grow < n)
                pa[j] = *(const float4*)&node_rep[(size_t)grow * D_IN + lc * 4];
        }
        pw = *(const float4*)&mlp_w[(size_t)wk * HID + wc * 4];
    }

    for (int t = 0; t < NTILES; t++) {
        __syncthreads();                 // previous tile's compute done
        // ---- STS current tile (transpose A, dup W) ----
        #pragma unroll
        for (int j = 0; j < 4; j++) {
            int r = (lr0 + 32 * j) ^ ssw;
            As[lc * 4 + 0][r] = pa[j].x;
            As[lc * 4 + 1][r] = pa[j].y;
            As[lc * 4 + 2][r] = pa[j].z;
            As[lc * 4 + 3][r] = pa[j].w;
        }
        Wd[wk][wc * 4 + 0] = dupf(pw.x);
        Wd[wk][wc * 4 + 1] = dupf(pw.y);
        Wd[wk][wc * 4 + 2] = dupf(pw.z);
        Wd[wk][wc * 4 + 3] = dupf(pw.w);
        __syncthreads();

        // ---- prefetch next tile while computing this one ----
        if (t + 1 < NTILES) {
            const int kc = (t + 1) * KC;
            #pragma unroll
            for (int j = 0; j < 4; j++) {
                int grow = row0 + lr0 + 32 * j;
                float4 v = make_float4(0.f, 0.f, 0.f, 0.f);
                if (grow < n)
                    v = *(const float4*)&node_rep[(size_t)grow * D_IN + kc + lc * 4];
                pa[j] = v;
            }
            pw = *(const float4*)&mlp_w[(size_t)(kc + wk) * HID + wc * 4];
        }

        // ---- compute 32 k's: per k 1 LDS.128 A + 2 LDS.128 W + 8 FFMA2 ----
        #pragma unroll
        for (int g = 0; g < 4; g++) {
            const int sw = (g & 1) * 8;                    // undo store swizzle
            const float* ab = &As[g * 8][w * 16 + ((rq * 4) ^ sw)];
            const ull*   wb = &Wd[g * 8][cq * 4];
            #pragma unroll
            for (int kk = 0; kk < 8; kk++) {
                ulonglong2 a  = *(const ulonglong2*)(ab + kk * ASTR);
                ulonglong2 w0 = *(const ulonglong2*)(wb + kk * WSTR);
                ulonglong2 w1 = *(const ulonglong2*)(wb + kk * WSTR + 2);
                acc[0][0] = ffma2(a.x, w0.x, acc[0][0]);
                acc[0][1] = ffma2(a.y, w0.x, acc[0][1]);
                acc[1][0] = ffma2(a.x, w0.y, acc[1][0]);
                acc[1][1] = ffma2(a.y, w0.y, acc[1][1]);
                acc[2][0] = ffma2(a.x, w1.x, acc[2][0]);
                acc[2][1] = ffma2(a.y, w1.x, acc[2][1]);
                acc[3][0] = ffma2(a.x, w1.y, acc[3][0]);
                acc[3][1] = ffma2(a.y, w1.y, acc[3][1]);
            }
        }
    }
    __syncthreads();   // GEMM SMEM dead; safe to overwrite with Hs

    // ---- epilogue: acc -> Hs (+bias). lane rows R0..R0+3, cols cq*4..+3 ----
    #pragma unroll
    for (int c = 0; c < 4; c++) {
        const int col = cq * 4 + c;
        const float b = mlpbs[col];
        Hs[R0 + 0][col] = __uint_as_float((unsigned)(acc[c][0]      )) + b;
        Hs[R0 + 1][col] = __uint_as_float((unsigned)(acc[c][0] >> 32)) + b;
        Hs[R0 + 2][col] = __uint_as_float((unsigned)(acc[c][1]      )) + b;
        Hs[R0 + 3][col] = __uint_as_float((unsigned)(acc[c][1] >> 32)) + b;
    }
    __syncthreads();

    // ---- KAN layer 0 (32 -> 6): 2 threads per row, 16 dims each ----
    {
        const int row  = tid >> 1;
        const int half = tid & 1;
        float acc6[W1] = {0.f, 0.f, 0.f, 0.f, 0.f, 0.f};
        #pragma unroll 1
        for (int ii = 0; ii < 16; ii++) {
            int i   = half * 16 + ii;
            float x = Hs[row][i];
            float Bv[5]; int ix[5];
            basis5m(x, Bv, ix);
            float s = silu_f(x);
            #pragma unroll
            for (int o = 0; o < W1; o++) {
                float d = dot5(csc0[i][o], Bv, ix);
                acc6[o] = fmaf(s, wb0s[i][o], acc6[o] + d);
            }
        }
        #pragma unroll
        for (int o = 0; o < W1; o++) part[row][half][o] = acc6[o];
    }
    __syncthreads();

    // ---- KAN layer 1 (6 -> 1) + store ----
    if (tid < RPB && row0 + tid < n) {
        float res = b1s;
        #pragma unroll 1
        for (int i = 0; i < W1; i++) {
            float x = part[tid][0][i] + part[tid][1][i] + b0s[i];
            float Bv[5]; int ix[5];
            basis5m(x, Bv, ix);
            res += dot5(csc1[i], Bv, ix) + silu_f(x) * wb1s[i];
        }
        out[row0 + tid] = res;
    }
}

extern "C" void kernel_launch(void* const* d_in, const int* in_sizes, int n_in,
                              void* d_out, int out_size) {
    const float* node_rep = (const float*)d_in[0];
    const float* mlp_w    = (const float*)d_in[1];
    const float* mlp_b    = (const float*)d_in[2];
    const float* coef0    = (const float*)d_in[3];
    const float* wb0      = (const float*)d_in[4];
    const float* ws0      = (const float*)d_in[5];
    const float* b0       = (const float*)d_in[6];
    const float* coef1    = (const float*)d_in[7];
    const float* wb1      = (const float*)d_in[8];
    const float* ws1      = (const float*)d_in[9];
    const float* b1       = (const float*)d_in[10];

    int n = out_size;                       // 300000 rows, one output each
    int grid = (n + RPB - 1) / RPB;
    kan_fused_kernel<<<grid, NTHR>>>(node_rep, mlp_w, mlp_b, coef0, wb0, ws0,
                                     b0, coef1, wb1, ws1, b1,
                                     (float*)d_out, n);
}

// round 6
// speedup vs baseline: 1.4775x; 1.4775x over previous
#include <cuda_runtime.h>

typedef unsigned long long ull;

#define D_IN 992
#define HID  32
#define W1   6
#define NB   12
#define KC   32               // k-chunk
#define RPB  128              // rows per block
#define NTHR 256
#define NTILES (D_IN / KC)    // 31
#define ASTR 132              // float stride of As row (16B-aligned, padded)

__device__ __forceinline__ ull ffma2(ull a, ull b, ull c) {
    ull d;
    asm("fma.rn.f32x2 %0, %1, %2, %3;" : "=l"(d) : "l"(a), "l"(b), "l"(c));
    return d;
}

__device__ __forceinline__ ull dupf(float f) {
    unsigned r = __float_as_uint(f);
    return (((ull)r) << 32) | (ull)r;
}

// Compact degree-4 uniform B-spline: 5 nonzero basis values + masked,
// clamped coefficient indices. Knots t_j = (j-4)*0.25 - 1  <=>  u=(x+2)*4.
__device__ __forceinline__ void basis5m(float x, float Bv[5], int ix[5]) {
    float u  = (x + 2.0f) * 4.0f;
    float fj = floorf(u);
    int   j0 = (int)fj;
    float s  = u - fj;                 // in [0,1)
    float B0, B1, B2, B3, B4;
    B1 = s;  B0 = 1.0f - s;
    B2 = 0.5f * (s * B1);
    B1 = 0.5f * ((s + 1.0f) * B0 + (2.0f - s) * B1);
    B0 = 0.5f * ((1.0f - s) * B0);
    const float i3 = (1.0f / 3.0f);
    B3 = i3 * (s * B2);
    B2 = i3 * ((s + 1.0f) * B1 + (3.0f - s) * B2);
    B1 = i3 * ((s + 2.0f) * B0 + (2.0f - s) * B1);
    B0 = i3 * ((1.0f - s) * B0);
    B4 = 0.25f * (s * B3);
    B3 = 0.25f * ((s + 1.0f) * B2 + (4.0f - s) * B3);
    B2 = 0.25f * ((s + 2.0f) * B1 + (3.0f - s) * B2);
    B1 = 0.25f * ((s + 3.0f) * B0 + (2.0f - s) * B1);
    B0 = 0.25f * ((1.0f - s) * B0);
    const bool vr = (j0 >= 0) && (j0 < 16);   // x in [-2,2) else all-zero
    float Bt[5] = {B0, B1, B2, B3, B4};
    #pragma unroll
    for (int m = 0; m < 5; m++) {
        int  id = j0 - 4 + m;                 // basis index into 0..11
        bool v  = vr && (id >= 0) && (id < 12);
        ix[m] = v ? id : 0;
        Bv[m] = v ? Bt[m] : 0.0f;
    }
}

__device__ __forceinline__ float dot5(const float* __restrict__ c,
                                      const float Bv[5], const int ix[5]) {
    float s = Bv[0] * c[ix[0]];
    s = fmaf(Bv[1], c[ix[1]], s);
    s = fmaf(Bv[2], c[ix[2]], s);
    s = fmaf(Bv[3], c[ix[3]], s);
    s = fmaf(Bv[4], c[ix[4]], s);
    return s;
}

__device__ __forceinline__ float silu_f(float x) {
    return x / (1.0f + __expf(-x));
}

__global__ __launch_bounds__(NTHR, 2)
void kan_fused_kernel(const float* __restrict__ node_rep,
                      const float* __restrict__ mlp_w,
                      const float* __restrict__ mlp_b,
                      const float* __restrict__ coef0,
                      const float* __restrict__ wb0,
                      const float* __restrict__ ws0,
                      const float* __restrict__ b0,
                      const float* __restrict__ coef1,
                      const float* __restrict__ wb1,
                      const float* __restrict__ ws1,
                      const float* __restrict__ b1,
                      float* __restrict__ out, int n)
{
    // GEMM tiles (As + Wp) aliased with Hs: GEMM region dead once hidden done.
    // As: [32][132] floats = 16896B;  Wp: [32][4 ull-quads] = 32*32 ull = 8192B
    __shared__ __align__(16) char buf[KC * ASTR * 4 + KC * 32 * 8];    // 25088B
    float (*As)[ASTR]    = (float (*)[ASTR])buf;                       // [32][132]
    ull* Wp              = (ull*)(buf + KC * ASTR * 4);                // [32][32]
    float (*Hs)[HID + 1] = (float (*)[HID + 1])buf;                    // [128][33]

    __shared__ __align__(16) float csc0[HID][W1][NB];   // coef0 * ws0
    __shared__ float wb0s[HID][W1];
    __shared__ float part[RPB][2][W1];
    __shared__ __align__(16) float csc1[W1][NB];        // coef1 * ws1
    __shared__ float wb1s[W1];
    __shared__ float b0s[W1];
    __shared__ float mlpbs[HID];
    __shared__ float b1s;

    const int tid  = threadIdx.x;
    const int row0 = blockIdx.x * RPB;

    // ---- stage small params (prescale spline coefs by w_sp) ----
    for (int idx = tid; idx < HID * W1 * NB; idx += NTHR)
        (&csc0[0][0][0])[idx] = coef0[idx] * ws0[idx / NB];
    if (tid < HID * W1) (&wb0s[0][0])[tid] = wb0[tid];
    if (tid < W1 * NB)  (&csc1[0][0])[tid] = coef1[tid] * ws1[tid / NB];
    if (tid < W1) { wb1s[tid] = wb1[tid]; b0s[tid] = b0[tid]; }
    if (tid < HID) mlpbs[tid] = mlp_b[tid];
    if (tid == 0) b1s = b1[0];

    // ---- GEMM thread geometry: warp owns 16 rows x 32 cols ----
    const int w  = tid >> 5;            // warp 0..7 -> rows w*16..w*16+15
    const int rq = (tid >> 3) & 3;      // 4-row patch within warp rows
    const int cq = tid & 7;             // 4-col patch (cols cq*4..cq*4+3)
    const int R0 = w * 16 + rq * 4;

    ull acc[4][2];                      // [col][row-pair]; 16 regs
    #pragma unroll
    for (int c = 0; c < 4; c++) { acc[c][0] = 0ull; acc[c][1] = 0ull; }

    // loader coordinates (R1's proven staging for A)
    const int lc  = tid & 7;       // float4 chunk of a 32-k row
    const int lr0 = tid >> 3;      // base row (r = lr0 + 32j)
    const int wk  = tid >> 3;      // W: k row (0..31)
    const int wc  = tid & 7;       // W: float4 chunk (0..7) -> cols wc*4..+3
    const int ssw = ((lc >> 1) & 1) * 8;   // store-side row swizzle (bit3 of k)

    float4 pa[4];
    float4 pw;

    // prologue: prefetch tile 0
    {
        #pragma unroll
        for (int j = 0; j < 4; j++) {
            int grow = row0 + lr0 + 32 * j;
            pa[j] = make_float4(0.f, 0.f, 0.f, 0.f);
            if (grow < n)
                pa[j] = *(const float4*)&node_rep[(size_t)grow * D_IN + lc * 4];
        }
        pw = *(const float4*)&mlp_w[(size_t)wk * HID + wc * 4];
    }

    for (int t = 0; t < NTILES; t++) {
        __syncthreads();                 // previous tile's compute done
        // ---- STS current tile ----
        #pragma unroll
        for (int j = 0; j < 4; j++) {
            int r = (lr0 + 32 * j) ^ ssw;
            As[lc * 4 + 0][r] = pa[j].x;
            As[lc * 4 + 1][r] = pa[j].y;
            As[lc * 4 + 2][r] = pa[j].z;
            As[lc * 4 + 3][r] = pa[j].w;
        }
        // W dup'd into two 128B planes per k:
        //   plane0[cq] = {dup(w[cq*4+0]), dup(w[cq*4+1])}
        //   plane1[cq] = {dup(w[cq*4+2]), dup(w[cq*4+3])}
        {
            ull* wrow = Wp + wk * 32;                 // 32 ulls per k row
            *(ulonglong2*)(wrow + wc * 2)      = make_ulonglong2(dupf(pw.x), dupf(pw.y));
            *(ulonglong2*)(wrow + 16 + wc * 2) = make_ulonglong2(dupf(pw.z), dupf(pw.w));
        }
        __syncthreads();

        // ---- prefetch next tile while computing this one ----
        if (t + 1 < NTILES) {
            const int kc = (t + 1) * KC;
            #pragma unroll
            for (int j = 0; j < 4; j++) {
                int grow = row0 + lr0 + 32 * j;
                float4 v = make_float4(0.f, 0.f, 0.f, 0.f);
                if (grow < n)
                    v = *(const float4*)&node_rep[(size_t)grow * D_IN + kc + lc * 4];
                pa[j] = v;
            }
            pw = *(const float4*)&mlp_w[(size_t)(kc + wk) * HID + wc * 4];
        }

        // ---- compute 32 k's: per k 3 lane-contiguous LDS.128 + 8 FFMA2 ----
        #pragma unroll
        for (int g = 0; g < 4; g++) {
            const int sw = (g & 1) * 8;                    // undo store swizzle
            const float* ab = &As[g * 8][w * 16 + ((rq * 4) ^ sw)];
            const ull*   wb = Wp + (g * 8) * 32 + cq * 2;
            #pragma unroll
            for (int kk = 0; kk < 8; kk++) {
                ulonglong2 a   = *(const ulonglong2*)(ab + kk * ASTR);
                ulonglong2 w01 = *(const ulonglong2*)(wb + kk * 32);
                ulonglong2 w23 = *(const ulonglong2*)(wb + kk * 32 + 16);
                acc[0][0] = ffma2(a.x, w01.x, acc[0][0]);
                acc[0][1] = ffma2(a.y, w01.x, acc[0][1]);
                acc[1][0] = ffma2(a.x, w01.y, acc[1][0]);
                acc[1][1] = ffma2(a.y, w01.y, acc[1][1]);
                acc[2][0] = ffma2(a.x, w23.x, acc[2][0]);
                acc[2][1] = ffma2(a.y, w23.x, acc[2][1]);
                acc[3][0] = ffma2(a.x, w23.y, acc[3][0]);
                acc[3][1] = ffma2(a.y, w23.y, acc[3][1]);
            }
        }
    }
    __syncthreads();   // GEMM SMEM dead; safe to overwrite with Hs

    // ---- epilogue: acc -> Hs (+bias). lane rows R0..R0+3, cols cq*4..+3 ----
    #pragma unroll
    for (int c = 0; c < 4; c++) {
        const int col = cq * 4 + c;
        const float b = mlpbs[col];
        Hs[R0 + 0][col] = __uint_as_float((unsigned)(acc[c][0]      )) + b;
        Hs[R0 + 1][col] = __uint_as_float((unsigned)(acc[c][0] >> 32)) + b;
        Hs[R0 + 2][col] = __uint_as_float((unsigned)(acc[c][1]      )) + b;
        Hs[R0 + 3][col] = __uint_as_float((unsigned)(acc[c][1] >> 32)) + b;
    }
    __syncthreads();

    // ---- KAN layer 0 (32 -> 6): 2 threads per row, 16 dims each ----
    {
        const int row  = tid >> 1;
        const int half = tid & 1;
        float acc6[W1] = {0.f, 0.f, 0.f, 0.f, 0.f, 0.f};
        #pragma unroll 1
        for (int ii = 0; ii < 16; ii++) {
            int i   = half * 16 + ii;
            float x = Hs[row][i];
            float Bv[5]; int ix[5];
            basis5m(x, Bv, ix);
            float s = silu_f(x);
            #pragma unroll
            for (int o = 0; o < W1; o++) {
                float d = dot5(csc0[i][o], Bv, ix);
                acc6[o] = fmaf(s, wb0s[i][o], acc6[o] + d);
            }
        }
        #pragma unroll
        for (int o = 0; o < W1; o++) part[row][half][o] = acc6[o];
    }
    __syncthreads();

    // ---- KAN layer 1 (6 -> 1) + store ----
    if (tid < RPB && row0 + tid < n) {
        float res = b1s;
        #pragma unroll 1
        for (int i = 0; i < W1; i++) {
            float x = part[tid][0][i] + part[tid][1][i] + b0s[i];
            float Bv[5]; int ix[5];
            basis5m(x, Bv, ix);
            res += dot5(csc1[i], Bv, ix) + silu_f(x) * wb1s[i];
        }
        out[row0 + tid] = res;
    }
}

extern "C" void kernel_launch(void* const* d_in, const int* in_sizes, int n_in,
                              void* d_out, int out_size) {
    const float* node_rep = (const float*)d_in[0];
    const float* mlp_w    = (const float*)d_in[1];
    const float* mlp_b    = (const float*)d_in[2];
    const float* coef0    = (const float*)d_in[3];
    const float* wb0      = (const float*)d_in[4];
    const float* ws0      = (const float*)d_in[5];
    const float* b0       = (const float*)d_in[6];
    const float* coef1    = (const float*)d_in[7];
    const float* wb1      = (const float*)d_in[8];
    const float* ws1      = (const float*)d_in[9];
    const float* b1       = (const float*)d_in[10];

    int n = out_size;                       // 300000 rows, one output each
    int grid = (n + RPB - 1) / RPB;
    kan_fused_kernel<<<grid, NTHR>>>(node_rep, mlp_w, mlp_b, coef0, wb0, ws0,
                                     b0, coef1, wb1, ws1, b1,
                                     (float*)d_out, n);
}

// round 8
// speedup vs baseline: 2.9156x; 1.9733x over previous
#include <cuda_runtime.h>

typedef unsigned long long ull;

#define D_IN   992
#define HID    32
#define W1     6
#define NB     12
#define KC     16               // k per tile
#define RPB    256              // rows per block
#define NTHR   128
#define NTILES 62               // 62*16 = 992
#define ASTR   260              // words per k-row of As (mult of 4; swizzle handles banks)
#define WSTR   36               // words per k-row of Ws

__device__ __forceinline__ ull ffma2(ull a, ull b, ull c) {
    ull d;
    asm("fma.rn.f32x2 %0, %1, %2, %3;" : "=l"(d) : "l"(a), "l"(b), "l"(c));
    return d;
}
__device__ __forceinline__ ull dup64(float a) {
    ull d;
    asm("mov.b64 %0, {%1, %1};" : "=l"(d) : "f"(a));
    return d;
}

// Compact degree-4 uniform B-spline: 5 nonzero values + masked clamped indices.
__device__ __forceinline__ void basis5m(float x, float Bv[5], int ix[5]) {
    float u  = (x + 2.0f) * 4.0f;
    float fj = floorf(u);
    int   j0 = (int)fj;
    float s  = u - fj;
    float B0, B1, B2, B3, B4;
    B1 = s;  B0 = 1.0f - s;
    B2 = 0.5f * (s * B1);
    B1 = 0.5f * ((s + 1.0f) * B0 + (2.0f - s) * B1);
    B0 = 0.5f * ((1.0f - s) * B0);
    const float i3 = (1.0f / 3.0f);
    B3 = i3 * (s * B2);
    B2 = i3 * ((s + 1.0f) * B1 + (3.0f - s) * B2);
    B1 = i3 * ((s + 2.0f) * B0 + (2.0f - s) * B1);
    B0 = i3 * ((1.0f - s) * B0);
    B4 = 0.25f * (s * B3);
    B3 = 0.25f * ((s + 1.0f) * B2 + (4.0f - s) * B3);
    B2 = 0.25f * ((s + 2.0f) * B1 + (3.0f - s) * B2);
    B1 = 0.25f * ((s + 3.0f) * B0 + (2.0f - s) * B1);
    B0 = 0.25f * ((1.0f - s) * B0);
    const bool vr = (j0 >= 0) && (j0 < 16);
    float Bt[5] = {B0, B1, B2, B3, B4};
    #pragma unroll
    for (int m = 0; m < 5; m++) {
        int  id = j0 - 4 + m;
        bool v  = vr && (id >= 0) && (id < 12);
        ix[m] = v ? id : 0;
        Bv[m] = v ? Bt[m] : 0.0f;
    }
}

__device__ __forceinline__ float silu_f(float x) {
    return x / (1.0f + __expf(-x));
}

// smem byte offsets
#define WS_OFF   16640           // after As (16*260*4)
#define GEMM_REG 33792           // params start after the Hs alias region
#define SMEM_SZ  44352

__global__ __launch_bounds__(NTHR, 3)
void kan_fused_kernel(const float* __restrict__ node_rep,
                      const float* __restrict__ mlp_w,
                      const float* __restrict__ mlp_b,
                      const float* __restrict__ coef0,
                      const float* __restrict__ wb0,
                      const float* __restrict__ ws0,
                      const float* __restrict__ b0,
                      const float* __restrict__ coef1,
                      const float* __restrict__ wb1,
                      const float* __restrict__ ws1,
                      const float* __restrict__ b1,
                      float* __restrict__ out, int n)
{
    __shared__ __align__(16) char smem[SMEM_SZ];
    float* As = (float*)smem;                        // [16][260] (transposed A tile)
    float* Ws = (float*)(smem + WS_OFF);             // [16][36]  (row-major W tile)
    float (*Hs)[HID + 1] = (float (*)[HID + 1])smem; // [256][33] alias (post-GEMM)
    float* csc0T = (float*)(smem + GEMM_REG);        // [12][193]: [b*193 + i*6 + o]
    float* wb0s  = csc0T + 2316;                     // [32*6]
    float* csc1T = wb0s + 192;                       // [12][7]:  [b*7 + i]
    float* wb1s  = csc1T + 84;                       // [6]
    float* b0s   = wb1s + 6;                         // [6]
    float* mlpbs = b0s + 6;                          // [32]
    float* b1s   = mlpbs + 32;                       // [1]

    const int tid  = threadIdx.x;
    const int w    = tid >> 5;
    const int l    = tid & 31;
    const int row0 = blockIdx.x * RPB;

    // ---- stage params (prescaled, gather-transposed with odd strides) ----
    for (int idx = tid; idx < NB * HID * W1; idx += NTHR) {
        int b = idx / (HID * W1), r = idx % (HID * W1);
        int i = r / W1, o = r % W1;
        csc0T[b * 193 + r] = coef0[i * (W1 * NB) + o * NB + b] * ws0[r];
    }
    for (int idx = tid; idx < HID * W1; idx += NTHR)   // FIX: was `if (tid < 192)` with NTHR=128
        wb0s[idx] = wb0[idx];
    if (tid < NB * 7) {
        int b = tid / 7, i = tid % 7;
        if (i < W1) csc1T[tid] = coef1[i * NB + b] * ws1[i];
    }
    if (tid < W1) { wb1s[tid] = wb1[tid]; b0s[tid] = b0[tid]; }
    if (tid < HID) mlpbs[tid] = mlp_b[tid];
    if (tid == 0) b1s[0] = b1[0];

    // ---- GEMM geometry: warp w -> rows [w*64, w*64+64) ----
    const int rg = (tid >> 2) & 7;      // 8-row group
    const int cq = tid & 3;             // 8-col group (cols cq*8 .. +7)
    const int R0 = w * 64 + rg * 8;

    ull acc[8][4];                      // [row][colpair] f32x2; 64 regs
    #pragma unroll
    for (int r = 0; r < 8; r++)
        #pragma unroll
        for (int p = 0; p < 4; p++) acc[r][p] = 0ull;

    // ---- stager coordinates ----
    const int sr = w * 8 + (l >> 2);    // staging base row (rows sr + 32j)
    const int k4 = l & 3;               // 4-k chunk within tile (k = k4*4+q)
    const int wk = tid >> 3;            // W: k row (0..15)
    const int wc = tid & 7;             // W: float4 chunk (cols wc*4..+3)
    const int s1 = ((k4 >> 1) & 1) << 3; // store swizzle: XOR 8 keyed on bit3 of k

    float4 pa[8];
    float4 pw;

    // prologue: prefetch tile 0
    #pragma unroll
    for (int j = 0; j < 8; j++) {
        int gr = row0 + sr + 32 * j;
        pa[j] = make_float4(0.f, 0.f, 0.f, 0.f);
        if (gr < n)
            pa[j] = *(const float4*)&node_rep[(size_t)gr * D_IN + k4 * 4];
    }
    pw = *(const float4*)&mlp_w[(size_t)wk * HID + wc * 4];

    for (int t = 0; t < NTILES; t++) {
        __syncthreads();                 // previous tile's compute done
        // ---- STS A transposed (conflict-free by bank construction) ----
        {
            const int kb = k4 * 4;
            #pragma unroll
            for (int j = 0; j < 8; j++) {
                int rw = (sr + 32 * j) ^ s1;
                As[(kb + 0) * ASTR + rw] = pa[j].x;
                As[(kb + 1) * ASTR + rw] = pa[j].y;
                As[(kb + 2) * ASTR + rw] = pa[j].z;
                As[(kb + 3) * ASTR + rw] = pa[j].w;
            }
        }
        // ---- STS W row-major ----
        *(float4*)&Ws[wk * WSTR + wc * 4] = pw;
        __syncthreads();

        // ---- prefetch next tile ----
        if (t + 1 < NTILES) {
            const int kc = (t + 1) * KC;
            #pragma unroll
            for (int j = 0; j < 8; j++) {
                int gr = row0 + sr + 32 * j;
                float4 v = make_float4(0.f, 0.f, 0.f, 0.f);
                if (gr < n)
                    v = *(const float4*)&node_rep[(size_t)gr * D_IN + kc + k4 * 4];
                pa[j] = v;
            }
            pw = *(const float4*)&mlp_w[(size_t)(kc + wk) * HID + wc * 4];
        }

        // ---- compute 16 k: per k 4 LDS.128 + 8 MOV dups + 32 FFMA2 ----
        #pragma unroll
        for (int k = 0; k < KC; k++) {
            const int ksw = ((k >> 3) & 1) << 3;
            const float* ab = &As[k * ASTR + (R0 ^ ksw)];
            float4 a0 = *(const float4*)ab;
            float4 a1 = *(const float4*)(ab + 4);
            ull ad0 = dup64(a0.x), ad1 = dup64(a0.y), ad2 = dup64(a0.z), ad3 = dup64(a0.w);
            ull ad4 = dup64(a1.x), ad5 = dup64(a1.y), ad6 = dup64(a1.z), ad7 = dup64(a1.w);
            const ull* wbp = (const ull*)&Ws[k * WSTR] + cq * 4;
            ulonglong2 wA = *(const ulonglong2*)(wbp);
            ulonglong2 wB = *(const ulonglong2*)(wbp + 2);
            acc[0][0] = ffma2(ad0, wA.x, acc[0][0]);
            acc[0][1] = ffma2(ad0, wA.y, acc[0][1]);
            acc[0][2] = ffma2(ad0, wB.x, acc[0][2]);
            acc[0][3] = ffma2(ad0, wB.y, acc[0][3]);
            acc[1][0] = ffma2(ad1, wA.x, acc[1][0]);
            acc[1][1] = ffma2(ad1, wA.y, acc[1][1]);
            acc[1][2] = ffma2(ad1, wB.x, acc[1][2]);
            acc[1][3] = ffma2(ad1, wB.y, acc[1][3]);
            acc[2][0] = ffma2(ad2, wA.x, acc[2][0]);
            acc[2][1] = ffma2(ad2, wA.y, acc[2][1]);
            acc[2][2] = ffma2(ad2, wB.x, acc[2][2]);
            acc[2][3] = ffma2(ad2, wB.y, acc[2][3]);
            acc[3][0] = ffma2(ad3, wA.x, acc[3][0]);
            acc[3][1] = ffma2(ad3, wA.y, acc[3][1]);
            acc[3][2] = ffma2(ad3, wB.x, acc[3][2]);
            acc[3][3] = ffma2(ad3, wB.y, acc[3][3]);
            acc[4][0] = ffma2(ad4, wA.x, acc[4][0]);
            acc[4][1] = ffma2(ad4, wA.y, acc[4][1]);
            acc[4][2] = ffma2(ad4, wB.x, acc[4][2]);
            acc[4][3] = ffma2(ad4, wB.y, acc[4][3]);
            acc[5][0] = ffma2(ad5, wA.x, acc[5][0]);
            acc[5][1] = ffma2(ad5, wA.y, acc[5][1]);
            acc[5][2] = ffma2(ad5, wB.x, acc[5][2]);
            acc[5][3] = ffma2(ad5, wB.y, acc[5][3]);
            acc[6][0] = ffma2(ad6, wA.x, acc[6][0]);
            acc[6][1] = ffma2(ad6, wA.y, acc[6][1]);
            acc[6][2] = ffma2(ad6, wB.x, acc[6][2]);
            acc[6][3] = ffma2(ad6, wB.y, acc[6][3]);
            acc[7][0] = ffma2(ad7, wA.x, acc[7][0]);
            acc[7][1] = ffma2(ad7, wA.y, acc[7][1]);
            acc[7][2] = ffma2(ad7, wB.x, acc[7][2]);
            acc[7][3] = ffma2(ad7, wB.y, acc[7][3]);
        }
    }
    __syncthreads();   // GEMM SMEM dead; safe to overwrite with Hs

    // ---- epilogue: acc -> Hs (+bias) ----
    #pragma unroll
    for (int r = 0; r < 8; r++) {
        #pragma unroll
        for (int p = 0; p < 4; p++) {
            const int col = cq * 8 + 2 * p;
            Hs[R0 + r][col    ] = __uint_as_float((unsigned)(acc[r][p]      )) + mlpbs[col];
            Hs[R0 + r][col + 1] = __uint_as_float((unsigned)(acc[r][p] >> 32)) + mlpbs[col + 1];
        }
    }
    __syncthreads();

    // ---- KAN: each thread owns 2 full rows end-to-end ----
    #pragma unroll 1
    for (int rr = tid; rr < RPB; rr += NTHR) {
        const int grow = row0 + rr;
        float acc6[W1] = {0.f, 0.f, 0.f, 0.f, 0.f, 0.f};
        #pragma unroll 1
        for (int i = 0; i < HID; i++) {
            float x = Hs[rr][i];
            float Bv[5]; int ix[5];
            basis5m(x, Bv, ix);
            float s = silu_f(x);
            const int base = i * W1;
            int a0 = ix[0] * 193 + base, a1 = ix[1] * 193 + base,
                a2 = ix[2] * 193 + base, a3 = ix[3] * 193 + base,
                a4 = ix[4] * 193 + base;
            #pragma unroll
            for (int o = 0; o < W1; o++) {
                float d =      Bv[0] * csc0T[a0 + o];
                d = fmaf(Bv[1], csc0T[a1 + o], d);
                d = fmaf(Bv[2], csc0T[a2 + o], d);
                d = fmaf(Bv[3], csc0T[a3 + o], d);
                d = fmaf(Bv[4], csc0T[a4 + o], d);
                acc6[o] = fmaf(s, wb0s[base + o], acc6[o] + d);
            }
        }
        float res = b1s[0];
        #pragma unroll 1
        for (int i = 0; i < W1; i++) {
            float x = acc6[i] + b0s[i];
            float Bv[5]; int ix[5];
            basis5m(x, Bv, ix);
            float d =      Bv[0] * csc1T[ix[0] * 7 + i];
            d = fmaf(Bv[1], csc1T[ix[1] * 7 + i], d);
            d = fmaf(Bv[2], csc1T[ix[2] * 7 + i], d);
            d = fmaf(Bv[3], csc1T[ix[3] * 7 + i], d);
            d = fmaf(Bv[4], csc1T[ix[4] * 7 + i], d);
            res += d + silu_f(x) * wb1s[i];
        }
        if (grow < n) out[grow] = res;
    }
}

extern "C" void kernel_launch(void* const* d_in, const int* in_sizes, int n_in,
                              void* d_out, int out_size) {
    const float* node_rep = (const float*)d_in[0];
    const float* mlp_w    = (const float*)d_in[1];
    const float* mlp_b    = (const float*)d_in[2];
    const float* coef0    = (const float*)d_in[3];
    const float* wb0      = (const float*)d_in[4];
    const float* ws0      = (const float*)d_in[5];
    const float* b0       = (const float*)d_in[6];
    const float* coef1    = (const float*)d_in[7];
    const float* wb1      = (const float*)d_in[8];
    const float* ws1      = (const float*)d_in[9];
    const float* b1       = (const float*)d_in[10];

    int n = out_size;                       // 300000 rows, one output each
    int grid = (n + RPB - 1) / RPB;
    kan_fused_kernel<<<grid, NTHR>>>(node_rep, mlp_w, mlp_b, coef0, wb0, ws0,
                                     b0, coef1, wb1, ws1, b1,
                                     (float*)d_out, n);
}